// round 14
// baseline (speedup 1.0000x reference)
#include <cuda_runtime.h>
#include <cstdint>

#define D_IN      128
#define E_DIM     64
#define TOTAL     320      // 2*D_IN + E_DIM
#define HEADS     8
#define MAX_NODES 100000
#define TILE_E    128      // edges per tile buffer
#define ROW_PAD   68       // floats per padded smem row (272B)
#define NPT       4        // nodes per thread in K2 (weight-LDS amortization)

// ---- scratch (__device__ globals — no allocations allowed) ----
__device__ float g_weff_node[256 * HEADS];   // Weff rows 0..255, layout [d][h]
__device__ float g_weffE[E_DIM * HEADS];     // Weff rows 256..319, layout [k][h]
__device__ float g_beff[HEADS];              // b1 @ W2 + b2
__device__ float g_proj[MAX_NODES * 16];     // per-node: 8 origin-proj + 8 dest-proj

static __device__ __forceinline__ uint32_t smem_u32(const void* p) {
    return (uint32_t)__cvta_generic_to_shared(p);
}

// ============================================================================
// Kernel 1: Weff = W1 @ W2  (320x8), beff = b1 @ W2 + b2.   One warp per output.
// ============================================================================
__global__ void prep_kernel(const float* __restrict__ W1, const float* __restrict__ b1,
                            const float* __restrict__ W2, const float* __restrict__ b2) {
    int w    = (blockIdx.x * blockDim.x + threadIdx.x) >> 5;
    int lane = threadIdx.x & 31;
    if (w >= TOTAL * HEADS + HEADS) return;

    float s = 0.0f;
    if (w < TOTAL * HEADS) {
        int i = w >> 3;      // Weff row (0..319)
        int h = w & 7;       // head
        #pragma unroll
        for (int t = 0; t < 10; t++) {
            int j = lane + 32 * t;
            s += W1[i * TOTAL + j] * W2[j * HEADS + h];
        }
        #pragma unroll
        for (int o = 16; o > 0; o >>= 1) s += __shfl_down_sync(0xffffffffu, s, o);
        if (lane == 0) {
            if (i < 256) g_weff_node[i * HEADS + h] = s;
            else         g_weffE[(i - 256) * HEADS + h] = s;   // [k][h] layout
        }
    } else {
        int h = w - TOTAL * HEADS;
        #pragma unroll
        for (int t = 0; t < 10; t++) {
            int j = lane + 32 * t;
            s += b1[j] * W2[j * HEADS + h];
        }
        #pragma unroll
        for (int o = 16; o > 0; o >>= 1) s += __shfl_down_sync(0xffffffffu, s, o);
        if (lane == 0) g_beff[h] = s + b2[h];
    }
}

// ============================================================================
// Kernel 2 v2: per-node projections, NPT nodes per thread.
// Weight smem loads (broadcast LDS.128) amortized NPT x: 512 -> 128 per node.
// FMA count unchanged; independent accumulator chains per node for ILP.
// ============================================================================
__global__ __launch_bounds__(256) void node_proj_kernel(const float* __restrict__ x,
                                                        int n_nodes) {
    __shared__ float sw[256 * HEADS];   // 8 KB
    for (int i = threadIdx.x; i < 256 * HEADS; i += blockDim.x) sw[i] = g_weff_node[i];
    __syncthreads();

    int t    = threadIdx.x;
    int base = blockIdx.x * (256 * NPT);

    int  n[NPT];
    bool valid[NPT];
    const float4* xr[NPT];
    #pragma unroll
    for (int m = 0; m < NPT; m++) {
        n[m]     = base + m * 256 + t;
        valid[m] = (n[m] < n_nodes);
        int nc   = valid[m] ? n[m] : (n_nodes - 1);   // clamp: safe load, no write
        xr[m]    = reinterpret_cast<const float4*>(x + (size_t)nc * D_IN);
    }

    float acc[NPT][16];
    #pragma unroll
    for (int m = 0; m < NPT; m++)
        #pragma unroll
        for (int h = 0; h < 16; h++) acc[m][h] = 0.0f;

    for (int c = 0; c < D_IN / 4; c++) {
        float4 xv[NPT];
        #pragma unroll
        for (int m = 0; m < NPT; m++) xv[m] = __ldg(xr[m] + c);

        #pragma unroll
        for (int j = 0; j < 4; j++) {
            int d = 4 * c + j;
            const float4* wo = reinterpret_cast<const float4*>(sw + d * HEADS);
            float4 w0 = wo[0], w1 = wo[1];
            const float4* wd = reinterpret_cast<const float4*>(sw + (128 + d) * HEADS);
            float4 v0 = wd[0], v1 = wd[1];

            #pragma unroll
            for (int m = 0; m < NPT; m++) {
                float xs = reinterpret_cast<const float*>(&xv[m])[j];
                acc[m][0]  += xs * w0.x;  acc[m][1]  += xs * w0.y;
                acc[m][2]  += xs * w0.z;  acc[m][3]  += xs * w0.w;
                acc[m][4]  += xs * w1.x;  acc[m][5]  += xs * w1.y;
                acc[m][6]  += xs * w1.z;  acc[m][7]  += xs * w1.w;
                acc[m][8]  += xs * v0.x;  acc[m][9]  += xs * v0.y;
                acc[m][10] += xs * v0.z;  acc[m][11] += xs * v0.w;
                acc[m][12] += xs * v1.x;  acc[m][13] += xs * v1.y;
                acc[m][14] += xs * v1.z;  acc[m][15] += xs * v1.w;
            }
        }
    }

    #pragma unroll
    for (int m = 0; m < NPT; m++) {
        if (valid[m]) {
            float4* pr = reinterpret_cast<float4*>(g_proj + (size_t)n[m] * 16);
            pr[0] = make_float4(acc[m][0],  acc[m][1],  acc[m][2],  acc[m][3]);
            pr[1] = make_float4(acc[m][4],  acc[m][5],  acc[m][6],  acc[m][7]);
            pr[2] = make_float4(acc[m][8],  acc[m][9],  acc[m][10], acc[m][11]);
            pr[3] = make_float4(acc[m][12], acc[m][13], acc[m][14], acc[m][15]);
        }
    }
}

// ============================================================================
// Kernel 3: edge pass, cp.async double-buffered + __stcs (known-good R11).
// ============================================================================
#define STILE_BUF (TILE_E * ROW_PAD)          // 8704 floats
#define SMEM_FLOATS (1024 + 2 * STILE_BUF)    // 18432 floats = 73728 B

__global__ __launch_bounds__(TILE_E) void edge_kernel(const int* __restrict__ ei,
                                                      const float* __restrict__ ee,
                                                      float* __restrict__ out,
                                                      int n_edges, int n_tiles) {
    extern __shared__ float smem[];
    float* swE   = smem;                       // 512 floats
    int*   sei   = (int*)(smem + 512);         // 512 ints
    float* stile = smem + 1024;

    int t = threadIdx.x;

    reinterpret_cast<float4*>(swE)[t] = reinterpret_cast<const float4*>(g_weffE)[t];
    float bh[8];
    #pragma unroll
    for (int h = 0; h < 8; h++) bh[h] = g_beff[h];

    const float4* ee4 = reinterpret_cast<const float4*>(ee);
    long total_f4 = (long)n_edges * 16;

    auto stage = [&](int buf, int tile) {
        if (tile < n_tiles) {
            long base = (long)tile * TILE_E * 16;
            float* dstb = stile + buf * STILE_BUF;
            #pragma unroll
            for (int i = 0; i < 16; i++) {
                int f   = i * TILE_E + t;
                int row = f >> 4;
                int col = f & 15;
                uint32_t d = smem_u32(dstb + row * ROW_PAD + col * 4);
                const float4* s = ee4 + base + f;
                int sz = (base + f < total_f4) ? 16 : 0;
                asm volatile("cp.async.cg.shared.global [%0], [%1], 16, %2;\n"
                             :: "r"(d), "l"(s), "r"(sz));
            }
            if (t < 64) {
                int half = t >> 5;           // 0 = origin, 1 = dest
                int q    = t & 31;
                int e0   = tile * TILE_E;
                const int* s = ei + (size_t)half * n_edges + e0 + q * 4;
                uint32_t d = smem_u32(sei + buf * 256 + half * 128 + q * 4);
                int rem = n_edges - (e0 + q * 4);
                int sz  = rem >= 4 ? 16 : (rem > 0 ? rem * 4 : 0);
                asm volatile("cp.async.cg.shared.global [%0], [%1], 16, %2;\n"
                             :: "r"(d), "l"(s), "r"(sz));
            }
        }
        asm volatile("cp.async.commit_group;\n");
    };

    int stride = gridDim.x;
    int tile   = blockIdx.x;
    stage(0, tile);
    stage(1, tile + stride);

    int buf = 0;
    for (; tile < n_tiles; tile += stride) {
        asm volatile("cp.async.wait_group 1;\n");
        __syncthreads();

        int e = tile * TILE_E + t;
        if (e < n_edges) {
            int o = sei[buf * 256 + t];
            int d = sei[buf * 256 + 128 + t];
            const float4* po = reinterpret_cast<const float4*>(g_proj + (size_t)o * 16);
            const float4* pd = reinterpret_cast<const float4*>(g_proj + (size_t)d * 16 + 8);
            float4 a0 = __ldg(po), a1 = __ldg(po + 1);
            float4 b0 = __ldg(pd), b1 = __ldg(pd + 1);

            float acc[8];
            acc[0] = a0.x + b0.x + bh[0];  acc[1] = a0.y + b0.y + bh[1];
            acc[2] = a0.z + b0.z + bh[2];  acc[3] = a0.w + b0.w + bh[3];
            acc[4] = a1.x + b1.x + bh[4];  acc[5] = a1.y + b1.y + bh[5];
            acc[6] = a1.z + b1.z + bh[6];  acc[7] = a1.w + b1.w + bh[7];

            const float* rowp = stile + buf * STILE_BUF + t * ROW_PAD;
            #pragma unroll
            for (int c = 0; c < 16; c++) {
                float4 v = *reinterpret_cast<const float4*>(rowp + c * 4);
                float vs[4] = {v.x, v.y, v.z, v.w};
                #pragma unroll
                for (int j = 0; j < 4; j++) {
                    int k = c * 4 + j;
                    const float4* w = reinterpret_cast<const float4*>(swE + k * 8);
                    float4 w0 = w[0], w1 = w[1];
                    acc[0] += vs[j] * w0.x;  acc[1] += vs[j] * w0.y;
                    acc[2] += vs[j] * w0.z;  acc[3] += vs[j] * w0.w;
                    acc[4] += vs[j] * w1.x;  acc[5] += vs[j] * w1.y;
                    acc[6] += vs[j] * w1.z;  acc[7] += vs[j] * w1.w;
                }
            }

            float4* op = reinterpret_cast<float4*>(out + (size_t)e * HEADS);
            __stcs(op,     make_float4(acc[0], acc[1], acc[2], acc[3]));
            __stcs(op + 1, make_float4(acc[4], acc[5], acc[6], acc[7]));
        }
        __syncthreads();

        stage(buf, tile + 2 * stride);
        buf ^= 1;
    }
}

// ============================================================================
// launcher
// ============================================================================
extern "C" void kernel_launch(void* const* d_in, const int* in_sizes, int n_in,
                              void* d_out, int out_size) {
    const float* x   = (const float*)d_in[0];
    const int*   ei  = (const int*)d_in[1];
    const float* ee  = (const float*)d_in[2];
    const float* W1  = (const float*)d_in[3];
    const float* b1  = (const float*)d_in[4];
    const float* W2  = (const float*)d_in[5];
    const float* b2  = (const float*)d_in[6];
    float*       out = (float*)d_out;

    int n_nodes = in_sizes[0] / D_IN;
    int n_edges = in_sizes[1] / 2;

    static bool attr_set = false;   // idempotent; not a stream op
    if (!attr_set) {
        cudaFuncSetAttribute(edge_kernel, cudaFuncAttributeMaxDynamicSharedMemorySize,
                             SMEM_FLOATS * (int)sizeof(float));
        attr_set = true;
    }

    // K1: Weff/beff prep
    {
        int warps   = TOTAL * HEADS + HEADS;
        int threads = warps * 32;
        int blocks  = (threads + 255) / 256;
        prep_kernel<<<blocks, 256>>>(W1, b1, W2, b2);
    }

    // K2: node projections — NPT nodes per thread
    {
        int nodes_per_block = 256 * NPT;
        int blocks = (n_nodes + nodes_per_block - 1) / nodes_per_block;
        node_proj_kernel<<<blocks, 256>>>(x, n_nodes);
    }

    // K3: edge pass — cp.async double-buffered tiles + streaming out stores
    {
        int n_tiles = (n_edges + TILE_E - 1) / TILE_E;
        int blocks  = 444;                  // 148 SMs x 3 resident (72KB smem each)
        if (blocks > n_tiles) blocks = n_tiles;
        edge_kernel<<<blocks, TILE_E, SMEM_FLOATS * (int)sizeof(float)>>>(
            ei, ee, out, n_edges, n_tiles);
    }
}